// round 1
// baseline (speedup 1.0000x reference)
#include <cuda_runtime.h>
#include <cstdint>
#include <math.h>

#define H    8192      // DIM_HIDDEN
#define S    4096      // DIM_SOL (steps)
#define CTX  4096      // DIM_CONTEXT
#define CSZ  8         // cluster size
#define TPB  1024      // threads per CTA (CSZ*TPB == H)

// ---------------- device scratch (static, no allocs) ----------------
__device__ float  g_Wt[(size_t)S * H];   // transposed W[:, CTX:] -> row i = column i (128 MB)
__device__ float  g_a0[H];               // a0 = c + W[:, :CTX] @ context
__device__ double g_thr[S];              // logit(u_i) in fp64: s_i = (x_i > thr_i)

// ---------------- helpers ----------------
__device__ __forceinline__ float sigmoidf_fast(float x) {
    return __fdividef(1.0f, 1.0f + __expf(-x));
}
__device__ __forceinline__ float softplusf(float y) {
    // log(1+exp(y)), stable
    float t = fabsf(y);
    float r = log1pf(__expf(-t));
    return (y > 0.f) ? (y + r) : r;
}
__device__ __forceinline__ unsigned cluster_rank() {
    unsigned r; asm("mov.u32 %0, %%cluster_ctarank;" : "=r"(r)); return r;
}
__device__ __forceinline__ uint32_t smem_u32(const void* p) {
    return (uint32_t)__cvta_generic_to_shared(p);
}
__device__ __forceinline__ void remote_store64(uint32_t laddr, unsigned rank, unsigned long long v) {
    uint32_t raddr;
    asm volatile("mapa.shared::cluster.u32 %0, %1, %2;" : "=r"(raddr) : "r"(laddr), "r"(rank));
    asm volatile("st.relaxed.cluster.shared::cluster.b64 [%0], %1;" :: "r"(raddr), "l"(v) : "memory");
}
__device__ __forceinline__ unsigned long long slot_ld(const unsigned long long* p) {
    unsigned long long v;
    uint32_t a = smem_u32(p);
    asm volatile("ld.relaxed.cluster.shared::cta.b64 %0, [%1];" : "=l"(v) : "r"(a) : "memory");
    return v;
}
__device__ __forceinline__ void cluster_barrier() {
    asm volatile("barrier.cluster.arrive.aligned;" ::: "memory");
    asm volatile("barrier.cluster.wait.aligned;"   ::: "memory");
}

// ---------------- init kernel 1: a0 = c + W[:, :CTX] @ context ----------------
__global__ void gemv_kernel(const float* __restrict__ W,
                            const float* __restrict__ ctxv,
                            const float* __restrict__ c) {
    __shared__ float sred[256];
    int r = blockIdx.x;                                 // hidden row 0..H-1
    const float* row = W + (size_t)r * (CTX + S);
    float acc = 0.f;
    for (int k = threadIdx.x; k < CTX; k += 256)
        acc += row[k] * ctxv[k];
    sred[threadIdx.x] = acc;
    __syncthreads();
    for (int off = 128; off > 0; off >>= 1) {
        if (threadIdx.x < off) sred[threadIdx.x] += sred[threadIdx.x + off];
        __syncthreads();
    }
    if (threadIdx.x == 0) g_a0[r] = c[r] + sred[0];
}

// ---------------- init kernel 2: transpose W[:, CTX:] -> g_Wt[i][j] ----------------
__global__ void transpose_kernel(const float* __restrict__ W) {
    __shared__ float tile[32][33];
    int i0 = blockIdx.x * 32;   // step (sol) index base
    int j0 = blockIdx.y * 32;   // hidden index base
    int tx = threadIdx.x;
    #pragma unroll
    for (int t = 0; t < 4; t++) {
        int ty = threadIdx.y + t * 8;
        tile[ty][tx] = W[(size_t)(j0 + ty) * (CTX + S) + CTX + i0 + tx];
    }
    __syncthreads();
    #pragma unroll
    for (int t = 0; t < 4; t++) {
        int ty = threadIdx.y + t * 8;
        g_Wt[(size_t)(i0 + ty) * H + j0 + tx] = tile[tx][ty];
    }
}

// ---------------- init kernel 3: thresholds t_i = logit(u_i) (fp64) ----------------
__global__ void thr_kernel(const float* __restrict__ u) {
    int i = blockIdx.x * 256 + threadIdx.x;
    if (i < S) {
        double ud = (double)u[i];
        g_thr[i] = log(ud / (1.0 - ud));   // u==0 -> -inf (s always 1, matches u<p)
    }
}

// ---------------- main sequential kernel: 8-CTA cluster ----------------
__global__ void __cluster_dims__(CSZ, 1, 1) __launch_bounds__(TPB, 1)
nade_kernel(const float* __restrict__ V,
            const float* __restrict__ b,
            float* __restrict__ out,
            int out_size) {
    __shared__ unsigned long long slots[2][CSZ];  // tagged partials, ring of 2
    __shared__ float2 red[2][32];                 // per-warp candidate partials

    const unsigned rank = cluster_rank();
    const int tid  = threadIdx.x;
    const int wid  = tid >> 5;
    const int lane = tid & 31;
    const int j    = (int)rank * TPB + tid;       // my hidden element

    if (tid < 2 * CSZ) ((unsigned long long*)slots)[tid] = 0xFFFFFFFF00000000ULL;
    cluster_barrier();   // slots initialized everywhere before any remote store

    float a = g_a0[j];
    float h = sigmoidf_fast(a);

    // ---- prologue: send partial for step 0: d = V[0]·h ----
    {
        float e = V[j] * h;
        #pragma unroll
        for (int o = 16; o > 0; o >>= 1) e += __shfl_xor_sync(0xffffffffu, e, o);
        if (lane == 0) red[0][wid] = make_float2(e, e);
        __syncthreads();
        if (wid == 0) {
            float2 rr = red[0][lane];
            float d = rr.x;
            #pragma unroll
            for (int o = 16; o > 0; o >>= 1) d += __shfl_xor_sync(0xffffffffu, d, o);
            if (lane == 0) {
                unsigned long long pk = (unsigned long long)__float_as_uint(d); // tag 0 in hi bits
                uint32_t laddr = smem_u32(&slots[0][rank]);
                #pragma unroll
                for (int cta = 0; cta < CSZ; cta++) remote_store64(laddr, (unsigned)cta, pk);
            }
        }
    }

    // ---- register double-buffers (prefetch) ----
    float  w_c  = g_Wt[j];                       // Wt[0]
    float  w_n  = g_Wt[(size_t)1 * H + j];       // Wt[1]
    float  v_n  = V[(size_t)1 * H + j];          // V[1]
    float  v_n2 = V[(size_t)2 * H + j];          // V[2]
    float  b_c  = b[0], b_nx = b[1];
    double t_c  = g_thr[0], t_nx = g_thr[1];

    double logp = 0.0;
    const bool leader0 = (rank == 0 && tid == 0);

    for (int i = 0; i < S; i++) {
        const int par  = i & 1;
        const int parn = par ^ 1;

        // speculative candidates for step i+1's partial (independent of s_i)
        float h1 = sigmoidf_fast(a + w_c);
        float e0 = v_n * h;
        float e1 = v_n * h1;
        #pragma unroll
        for (int o = 16; o > 0; o >>= 1) {
            e0 += __shfl_xor_sync(0xffffffffu, e0, o);
            e1 += __shfl_xor_sync(0xffffffffu, e1, o);
        }
        if (lane == 0) red[parn][wid] = make_float2(e0, e1);

        // issue prefetches for future iterations (off critical path)
        int ipw = (i + 2 <= S - 1) ? i + 2 : S - 1;
        int ipv = (i + 3 <= S - 1) ? i + 3 : S - 1;
        float  w_f = g_Wt[(size_t)ipw * H + j];
        float  v_f = V[(size_t)ipv * H + j];
        float  b_f = b[ipw];
        double t_f = g_thr[ipw];

        __syncthreads();

        float q0 = 0.f, q1 = 0.f;
        if (wid == 0) {
            float2 rr = red[parn][lane];
            #pragma unroll
            for (int o = 16; o > 0; o >>= 1) {
                rr.x += __shfl_xor_sync(0xffffffffu, rr.x, o);
                rr.y += __shfl_xor_sync(0xffffffffu, rr.y, o);
            }
            q0 = rr.x; q1 = rr.y;
        }

        // ---- poll for step i's 8 partials (all threads, identical result) ----
        unsigned long long sv0, sv1, sv2, sv3, sv4, sv5, sv6, sv7;
        const unsigned tg = (unsigned)i;
        for (;;) {
            sv0 = slot_ld(&slots[par][0]);
            sv1 = slot_ld(&slots[par][1]);
            sv2 = slot_ld(&slots[par][2]);
            sv3 = slot_ld(&slots[par][3]);
            sv4 = slot_ld(&slots[par][4]);
            sv5 = slot_ld(&slots[par][5]);
            sv6 = slot_ld(&slots[par][6]);
            sv7 = slot_ld(&slots[par][7]);
            bool ok = ((unsigned)(sv0 >> 32) == tg) & ((unsigned)(sv1 >> 32) == tg)
                    & ((unsigned)(sv2 >> 32) == tg) & ((unsigned)(sv3 >> 32) == tg)
                    & ((unsigned)(sv4 >> 32) == tg) & ((unsigned)(sv5 >> 32) == tg)
                    & ((unsigned)(sv6 >> 32) == tg) & ((unsigned)(sv7 >> 32) == tg);
            if (ok) break;
        }
        // fixed-order sum -> identical D on every thread of every CTA
        float D = __uint_as_float((unsigned)sv0);
        D += __uint_as_float((unsigned)sv1);
        D += __uint_as_float((unsigned)sv2);
        D += __uint_as_float((unsigned)sv3);
        D += __uint_as_float((unsigned)sv4);
        D += __uint_as_float((unsigned)sv5);
        D += __uint_as_float((unsigned)sv6);
        D += __uint_as_float((unsigned)sv7);

        float x = b_c + D;
        bool  s = ((double)x > t_c);   // == (u_i < sigmoid(x)) by monotone logit transform

        // select + send partial for step i+1 (critical path tail)
        if (tid == 0 && (i + 1) < S) {
            float dsel = s ? q1 : q0;
            unsigned long long pk =
                ((unsigned long long)(unsigned)(i + 1) << 32) |
                (unsigned long long)__float_as_uint(dsel);
            uint32_t laddr = smem_u32(&slots[parn][rank]);
            #pragma unroll
            for (int cta = 0; cta < CSZ; cta++) remote_store64(laddr, (unsigned)cta, pk);
        }

        if (leader0) {
            out[i] = s ? 1.0f : 0.0f;
            if (i < S - 2) {
                // log p = -softplus(-x); log(1-p) = -softplus(x)
                logp -= (double)(s ? softplusf(-x) : softplusf(x));
            }
        }

        // commit state
        if (s) { a += w_c; h = h1; }

        // rotate prefetch buffers
        w_c = w_n;  w_n  = w_f;
        v_n = v_n2; v_n2 = v_f;
        b_c = b_nx; b_nx = b_f;
        t_c = t_nx; t_nx = t_f;
    }

    if (leader0) {
        out[S] = (float)logp;
        for (int k = S + 1; k < out_size; k++) out[k] = 0.f;  // safety fill
    }
    cluster_barrier();
}

// ---------------- launch ----------------
extern "C" void kernel_launch(void* const* d_in, const int* in_sizes, int n_in,
                              void* d_out, int out_size) {
    // Expected order: context(4096), u(4096), W(8192*8192), V(4096*8192), b(4096), c(8192)
    const float* ctxv = nullptr;
    const float* u    = nullptr;
    const float* W    = nullptr;
    const float* V    = nullptr;
    const float* b    = nullptr;
    const float* c    = nullptr;

    const int szW = (CTX + S) * (H / 1) ;        // 8192*8192 elems (fits in int as count? 67108864 yes)
    const int szV = S * H;                       // 33554432
    int n4seen = 0;
    for (int idx = 0; idx < n_in; idx++) {
        int sz = in_sizes[idx];
        const float* p = (const float*)d_in[idx];
        if (sz == szW)       W = p;
        else if (sz == szV)  V = p;
        else if (sz == H)    c = p;
        else if (sz == S) {                      // context, u, b in dict order
            if      (n4seen == 0) ctxv = p;
            else if (n4seen == 1) u    = p;
            else                  b    = p;
            n4seen++;
        }
    }
    // fallback to positional order if anything missing
    if (!ctxv) ctxv = (const float*)d_in[0];
    if (!u)    u    = (const float*)d_in[1];
    if (!W)    W    = (const float*)d_in[2];
    if (!V)    V    = (const float*)d_in[3];
    if (!b)    b    = (const float*)d_in[4];
    if (!c)    c    = (const float*)d_in[5];

    float* out = (float*)d_out;

    gemv_kernel<<<H, 256>>>(W, ctxv, c);
    transpose_kernel<<<dim3(S / 32, H / 32), dim3(32, 8)>>>(W);
    thr_kernel<<<(S + 255) / 256, 256>>>(u);
    nade_kernel<<<CSZ, TPB>>>(V, b, out, out_size);
}

// round 2
// speedup vs baseline: 1.5107x; 1.5107x over previous
#include <cuda_runtime.h>
#include <cstdint>
#include <math.h>

#define H    8192      // DIM_HIDDEN
#define S    4096      // DIM_SOL (steps)
#define CTX  4096      // DIM_CONTEXT
#define CSZ  8         // cluster size
#define NWW  8         // worker warps per CTA
#define WTH  256       // worker threads per CTA
#define EPT  4         // hidden elems per worker thread (256*4*8 = 8192)
#define TPB  320       // 8 worker warps + coordinator (wid 8) + logp (wid 9)

// ---------------- device scratch (static, no allocs) ----------------
__device__ float  g_Wt[(size_t)S * H];   // transposed W[:, CTX:]
__device__ float  g_a0[H];               // a0 = c + W[:, :CTX] @ context
__device__ float2 g_thr2[S];             // (t_hi, t_lo) two-float logit(u_i)

// ---------------- helpers ----------------
__device__ __forceinline__ float sigmoidf_fast(float x) {
    return __fdividef(1.0f, 1.0f + __expf(-x));
}
__device__ __forceinline__ float softplusf(float y) {
    float t = fabsf(y);
    float r = log1pf(__expf(-t));
    return (y > 0.f) ? (y + r) : r;
}
__device__ __forceinline__ unsigned cluster_rank() {
    unsigned r; asm("mov.u32 %0, %%cluster_ctarank;" : "=r"(r)); return r;
}
__device__ __forceinline__ uint32_t smem_u32(const void* p) {
    return (uint32_t)__cvta_generic_to_shared(p);
}
__device__ __forceinline__ void remote_store64(uint32_t laddr, unsigned rank, unsigned long long v) {
    uint32_t raddr;
    asm volatile("mapa.shared::cluster.u32 %0, %1, %2;" : "=r"(raddr) : "r"(laddr), "r"(rank));
    asm volatile("st.relaxed.cluster.shared::cluster.b64 [%0], %1;" :: "r"(raddr), "l"(v) : "memory");
}
__device__ __forceinline__ unsigned long long slot_ld(const unsigned long long* p) {
    unsigned long long v;
    uint32_t a = smem_u32(p);
    asm volatile("ld.relaxed.cluster.shared::cta.b64 %0, [%1];" : "=l"(v) : "r"(a) : "memory");
    return v;
}
__device__ __forceinline__ void cluster_barrier() {
    asm volatile("barrier.cluster.arrive.aligned;" ::: "memory");
    asm volatile("barrier.cluster.wait.aligned;"   ::: "memory");
}
// threshold compare: s = (x > t) with t = t_hi + t_lo (x is exact fp32)
__device__ __forceinline__ bool thr_cmp(float x, float2 t) {
    return (x > t.x) || ((x == t.x) && (t.y < 0.f));
}

// ---------------- init kernel 1: a0 = c + W[:, :CTX] @ context ----------------
__global__ void gemv_kernel(const float* __restrict__ W,
                            const float* __restrict__ ctxv,
                            const float* __restrict__ c) {
    __shared__ float sred[256];
    int r = blockIdx.x;
    const float* row = W + (size_t)r * (CTX + S);
    float acc = 0.f;
    for (int k = threadIdx.x; k < CTX; k += 256)
        acc += row[k] * ctxv[k];
    sred[threadIdx.x] = acc;
    __syncthreads();
    for (int off = 128; off > 0; off >>= 1) {
        if (threadIdx.x < off) sred[threadIdx.x] += sred[threadIdx.x + off];
        __syncthreads();
    }
    if (threadIdx.x == 0) g_a0[r] = c[r] + sred[0];
}

// ---------------- init kernel 2: transpose W[:, CTX:] -> g_Wt ----------------
__global__ void transpose_kernel(const float* __restrict__ W) {
    __shared__ float tile[32][33];
    int i0 = blockIdx.x * 32;   // step index base
    int j0 = blockIdx.y * 32;   // hidden index base
    int tx = threadIdx.x;
    #pragma unroll
    for (int t = 0; t < 4; t++) {
        int ty = threadIdx.y + t * 8;
        tile[ty][tx] = W[(size_t)(j0 + ty) * (CTX + S) + CTX + i0 + tx];
    }
    __syncthreads();
    #pragma unroll
    for (int t = 0; t < 4; t++) {
        int ty = threadIdx.y + t * 8;
        g_Wt[(size_t)(i0 + ty) * H + j0 + tx] = tile[tx][ty];
    }
}

// ---------------- init kernel 3: two-float thresholds ----------------
__global__ void thr_kernel(const float* __restrict__ u) {
    int i = blockIdx.x * 256 + threadIdx.x;
    if (i < S) {
        double ud = (double)u[i];
        double t  = log(ud / (1.0 - ud));
        float hi  = (float)t;
        float lo  = (float)(t - (double)hi);   // NaN if hi = +-inf; unused then
        g_thr2[i] = make_float2(hi, lo);
    }
}

// ---------------- main sequential kernel: 8-CTA cluster ----------------
__global__ void __cluster_dims__(CSZ, 1, 1) __launch_bounds__(TPB, 1)
nade_kernel(const float* __restrict__ V,
            const float* __restrict__ b,
            float* __restrict__ out,
            int out_size) {
    __shared__ unsigned long long slots[2][CSZ];   // remote per-CTA partials (tagged)
    __shared__ unsigned long long wp0[2][NWW];     // worker partials, s=0 branch (tagged)
    __shared__ unsigned long long wp1[2][NWW];     // worker partials, s=1 branch (tagged)
    __shared__ unsigned int       dec[2];          // decision word: (step<<1)|s
    __shared__ unsigned long long xw[16];          // x ring for logp warp (tagged)

    const unsigned rank = cluster_rank();
    const int tid  = threadIdx.x;
    const int wid  = tid >> 5;
    const int lane = tid & 31;
    const unsigned FULL = 0xffffffffu;

    if (tid < 2 * CSZ) ((unsigned long long*)slots)[tid] = 0xFFFFFFFF00000000ULL;
    if (tid < 2 * NWW) {
        ((unsigned long long*)wp0)[tid] = 0xFFFFFFFF00000000ULL;
        ((unsigned long long*)wp1)[tid] = 0xFFFFFFFF00000000ULL;
    }
    if (tid < 2)  dec[tid] = 0xFFFFFFFFu;
    if (tid < 16) xw[tid]  = 0xFFFFFFFF00000000ULL;
    __syncthreads();
    cluster_barrier();   // everyone's slots visible before any remote store

    volatile unsigned int*       decv = dec;
    volatile unsigned long long* xwv  = xw;

    if (wid < NWW) {
        // ================= worker warps =================
        const int base = (int)rank * (WTH * EPT) + tid;   // + e*WTH
        float a[EPT], h[EPT], h1[EPT];
        float wprev[EPT], wcur[EPT], wnext[EPT], vcur[EPT], vnext[EPT];

        #pragma unroll
        for (int e = 0; e < EPT; e++) {
            int j   = base + e * WTH;
            a[e]    = g_a0[j];
            h[e]    = sigmoidf_fast(a[e]);
            h1[e]   = h[e];
            wprev[e]= 0.f;
            wcur[e] = g_Wt[j];                          // W_0
            wnext[e]= g_Wt[(size_t)1 * H + j];          // W_1
            vcur[e] = V[(size_t)1 * H + j];             // V_1
            vnext[e]= V[(size_t)2 * H + j];             // V_2
        }

        // prologue: partial for step 0 = V_0 . h
        {
            float e0 = 0.f;
            #pragma unroll
            for (int e = 0; e < EPT; e++)
                e0 = fmaf(V[base + e * WTH], h[e], e0);
            #pragma unroll
            for (int o = 16; o > 0; o >>= 1)
                e0 += __shfl_xor_sync(FULL, e0, o);
            if (lane == 0) {
                unsigned long long pk = (unsigned long long)__float_as_uint(e0); // tag 0
                ((volatile unsigned long long*)wp0[0])[wid] = pk;
                ((volatile unsigned long long*)wp1[0])[wid] = pk;
            }
        }

        for (int p = 1; p < S; p++) {
            // prefetch future rows (independent of decision)
            int pw = (p + 1 < S) ? p + 1 : S - 1;
            int pv = (p + 2 < S) ? p + 2 : S - 1;
            float wf[EPT], vf[EPT];
            #pragma unroll
            for (int e = 0; e < EPT; e++) {
                wf[e] = g_Wt[(size_t)pw * H + base + e * WTH];
                vf[e] = V[(size_t)pv * H + base + e * WTH];
            }

            if (p >= 2) {
                const unsigned want = (unsigned)(p - 2);
                unsigned d;
                do { d = decv[(p - 2) & 1]; } while ((d >> 1) != want);
                float sm = (float)(d & 1);
                bool  sb = (d & 1);
                #pragma unroll
                for (int e = 0; e < EPT; e++) {
                    a[e] = fmaf(sm, wprev[e], a[e]);
                    h[e] = sb ? h1[e] : h[e];
                }
            }

            float e0 = 0.f, e1 = 0.f;
            #pragma unroll
            for (int e = 0; e < EPT; e++) {
                h1[e] = sigmoidf_fast(a[e] + wcur[e]);
                e0 = fmaf(vcur[e], h[e],  e0);
                e1 = fmaf(vcur[e], h1[e], e1);
            }
            #pragma unroll
            for (int o = 16; o > 0; o >>= 1) {
                e0 += __shfl_xor_sync(FULL, e0, o);
                e1 += __shfl_xor_sync(FULL, e1, o);
            }
            if (lane == 0) {
                unsigned long long tg = (unsigned long long)(unsigned)p << 32;
                ((volatile unsigned long long*)wp0[p & 1])[wid] = tg | __float_as_uint(e0);
                ((volatile unsigned long long*)wp1[p & 1])[wid] = tg | __float_as_uint(e1);
            }
            #pragma unroll
            for (int e = 0; e < EPT; e++) {
                wprev[e] = wcur[e]; wcur[e] = wnext[e]; wnext[e] = wf[e];
                vcur[e]  = vnext[e]; vnext[e] = vf[e];
            }
        }
    } else if (wid == NWW) {
        // ================= coordinator warp =================
        auto gather = [&](int step, float& Q0, float& Q1) {
            const unsigned want = (unsigned)step;
            const int par = step & 1;
            unsigned long long v = 0;
            if      (lane < 8)  v = ((volatile unsigned long long*)wp0[par])[lane];
            else if (lane < 16) v = ((volatile unsigned long long*)wp1[par])[lane - 8];
            while (!__all_sync(FULL, (lane >= 16) || ((unsigned)(v >> 32) == want))) {
                if      (lane < 8)  v = ((volatile unsigned long long*)wp0[par])[lane];
                else if (lane < 16) v = ((volatile unsigned long long*)wp1[par])[lane - 8];
            }
            float f = (lane < 16) ? __uint_as_float((unsigned)v) : 0.f;
            f += __shfl_xor_sync(FULL, f, 1);
            f += __shfl_xor_sync(FULL, f, 2);
            f += __shfl_xor_sync(FULL, f, 4);
            Q0 = f;
            Q1 = __shfl_xor_sync(FULL, f, 8);
        };

        float  bc = b[0],        bn = b[1];
        float2 tc = g_thr2[0],   tn = g_thr2[1];

        // prologue: send step-0 partial (both branches equal)
        {
            float q0, q1;
            gather(0, q0, q1);
            if (lane < 8) {
                unsigned long long pk = (unsigned long long)__float_as_uint(q0); // tag 0
                remote_store64(smem_u32(&slots[0][rank]), (unsigned)lane, pk);
            }
        }

        for (int i = 0; i < S; i++) {
            float q0n = 0.f, q1n = 0.f;
            if (i + 1 < S) gather(i + 1, q0n, q1n);   // usually ready; overlaps wait

            // poll the 8 remote slots for step i
            const unsigned want = (unsigned)i;
            unsigned long long sv = 0;
            if (lane < 8) sv = slot_ld(&slots[i & 1][lane]);
            while (!__all_sync(FULL, (lane >= 8) || ((unsigned)(sv >> 32) == want))) {
                if (lane < 8) sv = slot_ld(&slots[i & 1][lane]);
            }
            float D = (lane < 8) ? __uint_as_float((unsigned)sv) : 0.f;
            D += __shfl_xor_sync(FULL, D, 1);
            D += __shfl_xor_sync(FULL, D, 2);
            D += __shfl_xor_sync(FULL, D, 4);     // lanes 0-7: identical full sum

            float x = bc + D;
            bool  s = thr_cmp(x, tc);

            if ((i + 1 < S) && lane < 8) {        // critical tail: send first
                float dsel = s ? q1n : q0n;
                unsigned long long pk =
                    ((unsigned long long)(unsigned)(i + 1) << 32) |
                    (unsigned long long)__float_as_uint(dsel);
                remote_store64(smem_u32(&slots[(i + 1) & 1][rank]), (unsigned)lane, pk);
            }
            if (lane == 0) {
                decv[i & 1]  = ((unsigned)i << 1) | (unsigned)s;
                xwv[i & 15]  = ((unsigned long long)(unsigned)i << 32) |
                               (unsigned long long)__float_as_uint(x);
            }

            int ip = (i + 2 < S) ? i + 2 : S - 1;
            float bf = b[ip]; float2 tf = g_thr2[ip];
            bc = bn; bn = bf; tc = tn; tn = tf;
        }
    } else {
        // ================= logp/output warp (rank 0, lane 0 only) =================
        if (rank == 0 && lane == 0) {
            float2 tc = g_thr2[0], tn = g_thr2[1];
            double lp = 0.0;
            for (int i = 0; i < S; i++) {
                unsigned long long xv;
                do { xv = xwv[i & 15]; } while ((unsigned)(xv >> 32) != (unsigned)i);
                float x = __uint_as_float((unsigned)xv);
                bool  s = thr_cmp(x, tc);
                out[i] = s ? 1.0f : 0.0f;
                if (i < S - 2)
                    lp -= (double)(s ? softplusf(-x) : softplusf(x));
                int ip = (i + 2 < S) ? i + 2 : S - 1;
                float2 tf = g_thr2[ip];
                tc = tn; tn = tf;
            }
            out[S] = (float)lp;
            for (int k = S + 1; k < out_size; k++) out[k] = 0.f;
        }
    }

    cluster_barrier();   // no CTA exits while peers may still store to its smem
}

// ---------------- launch ----------------
extern "C" void kernel_launch(void* const* d_in, const int* in_sizes, int n_in,
                              void* d_out, int out_size) {
    const float* ctxv = nullptr;
    const float* u    = nullptr;
    const float* W    = nullptr;
    const float* V    = nullptr;
    const float* b    = nullptr;
    const float* c    = nullptr;

    const int szW = (CTX + S) * H;   // 67108864
    const int szV = S * H;           // 33554432
    int n4seen = 0;
    for (int idx = 0; idx < n_in; idx++) {
        int sz = in_sizes[idx];
        const float* p = (const float*)d_in[idx];
        if (sz == szW)       W = p;
        else if (sz == szV)  V = p;
        else if (sz == H)    c = p;
        else if (sz == S) {
            if      (n4seen == 0) ctxv = p;
            else if (n4seen == 1) u    = p;
            else                  b    = p;
            n4seen++;
        }
    }
    if (!ctxv) ctxv = (const float*)d_in[0];
    if (!u)    u    = (const float*)d_in[1];
    if (!W)    W    = (const float*)d_in[2];
    if (!V)    V    = (const float*)d_in[3];
    if (!b)    b    = (const float*)d_in[4];
    if (!c)    c    = (const float*)d_in[5];

    float* out = (float*)d_out;

    gemv_kernel<<<H, 256>>>(W, ctxv, c);
    transpose_kernel<<<dim3(S / 32, H / 32), dim3(32, 8)>>>(W);
    thr_kernel<<<(S + 255) / 256, 256>>>(u);
    nade_kernel<<<CSZ, TPB>>>(V, b, out, out_size);
}

// round 3
// speedup vs baseline: 1.8302x; 1.2114x over previous
#include <cuda_runtime.h>
#include <cstdint>
#include <math.h>

#define H    8192      // DIM_HIDDEN
#define S    4096      // DIM_SOL (steps)
#define CTX  4096      // DIM_CONTEXT
#define CSZ  8         // cluster size
#define NWW  8         // worker warps per CTA
#define WTH  256       // worker threads per CTA
#define EPT  4         // hidden elems per worker thread (256*4*8 = 8192)
#define TPB  320       // 8 worker warps + coordinator (wid 8) + logp (wid 9)

// ---------------- device scratch (static, no allocs) ----------------
__device__ float  g_Wt[(size_t)S * H];   // transposed W[:, CTX:]
__device__ float  g_a0[H];               // a0 = c + W[:, :CTX] @ context
__device__ float2 g_thr2[S];             // (t_hi, t_lo) two-float logit(u_i)

// ---------------- helpers ----------------
__device__ __forceinline__ float sigmoidf_fast(float x) {
    return __fdividef(1.0f, 1.0f + __expf(-x));
}
__device__ __forceinline__ float softplusf(float y) {
    float t = fabsf(y);
    float r = log1pf(__expf(-t));
    return (y > 0.f) ? (y + r) : r;
}
__device__ __forceinline__ unsigned cluster_rank() {
    unsigned r; asm("mov.u32 %0, %%cluster_ctarank;" : "=r"(r)); return r;
}
__device__ __forceinline__ uint32_t smem_u32(const void* p) {
    return (uint32_t)__cvta_generic_to_shared(p);
}
__device__ __forceinline__ void remote_store64(uint32_t laddr, unsigned rank, unsigned long long v) {
    uint32_t raddr;
    asm volatile("mapa.shared::cluster.u32 %0, %1, %2;" : "=r"(raddr) : "r"(laddr), "r"(rank));
    asm volatile("st.relaxed.cluster.shared::cluster.b64 [%0], %1;" :: "r"(raddr), "l"(v) : "memory");
}
__device__ __forceinline__ unsigned long long slot_ld(const unsigned long long* p) {
    unsigned long long v;
    uint32_t a = smem_u32(p);
    asm volatile("ld.relaxed.cluster.shared::cta.b64 %0, [%1];" : "=l"(v) : "r"(a) : "memory");
    return v;
}
__device__ __forceinline__ void cluster_barrier() {
    asm volatile("barrier.cluster.arrive.aligned;" ::: "memory");
    asm volatile("barrier.cluster.wait.aligned;"   ::: "memory");
}
// threshold compare: s = (x > t) with t = t_hi + t_lo (x is exact fp32)
__device__ __forceinline__ bool thr_cmp(float x, float2 t) {
    return (x > t.x) || ((x == t.x) && (t.y < 0.f));
}

// ---------------- init kernel 1: a0 = c + W[:, :CTX] @ context ----------------
__global__ void gemv_kernel(const float* __restrict__ W,
                            const float* __restrict__ ctxv,
                            const float* __restrict__ c) {
    __shared__ float sred[256];
    int r = blockIdx.x;
    const float* row = W + (size_t)r * (CTX + S);
    float acc = 0.f;
    for (int k = threadIdx.x; k < CTX; k += 256)
        acc += row[k] * ctxv[k];
    sred[threadIdx.x] = acc;
    __syncthreads();
    for (int off = 128; off > 0; off >>= 1) {
        if (threadIdx.x < off) sred[threadIdx.x] += sred[threadIdx.x + off];
        __syncthreads();
    }
    if (threadIdx.x == 0) g_a0[r] = c[r] + sred[0];
}

// ---------------- init kernel 2: transpose W[:, CTX:] -> g_Wt ----------------
__global__ void transpose_kernel(const float* __restrict__ W) {
    __shared__ float tile[32][33];
    int i0 = blockIdx.x * 32;   // step index base
    int j0 = blockIdx.y * 32;   // hidden index base
    int tx = threadIdx.x;
    #pragma unroll
    for (int t = 0; t < 4; t++) {
        int ty = threadIdx.y + t * 8;
        tile[ty][tx] = W[(size_t)(j0 + ty) * (CTX + S) + CTX + i0 + tx];
    }
    __syncthreads();
    #pragma unroll
    for (int t = 0; t < 4; t++) {
        int ty = threadIdx.y + t * 8;
        g_Wt[(size_t)(i0 + ty) * H + j0 + tx] = tile[tx][ty];
    }
}

// ---------------- init kernel 3: two-float thresholds ----------------
__global__ void thr_kernel(const float* __restrict__ u) {
    int i = blockIdx.x * 256 + threadIdx.x;
    if (i < S) {
        double ud = (double)u[i];
        double t  = log(ud / (1.0 - ud));
        float hi  = (float)t;
        float lo  = (float)(t - (double)hi);
        g_thr2[i] = make_float2(hi, lo);
    }
}

// ---------------- main sequential kernel: 8-CTA cluster ----------------
__global__ void __cluster_dims__(CSZ, 1, 1) __launch_bounds__(TPB, 1)
nade_kernel(const float* __restrict__ V,
            const float* __restrict__ b,
            float* __restrict__ out,
            int out_size) {
    __shared__ unsigned long long slots[2][CSZ];   // remote per-CTA partials (tagged)
    __shared__ unsigned long long wp0[2][NWW];     // worker partials, s=0 branch (tagged)
    __shared__ unsigned long long wp1[2][NWW];     // worker partials, s=1 branch (tagged)
    __shared__ unsigned int       dec[2];          // decision word: (step<<1)|s
    __shared__ unsigned long long xw[16];          // x ring for logp warp (tagged)

    const unsigned rank = cluster_rank();
    const int tid  = threadIdx.x;
    const int wid  = tid >> 5;
    const int lane = tid & 31;
    const unsigned FULL = 0xffffffffu;

    if (tid < 2 * CSZ) ((unsigned long long*)slots)[tid] = 0xFFFFFFFF00000000ULL;
    if (tid < 2 * NWW) {
        ((unsigned long long*)wp0)[tid] = 0xFFFFFFFF00000000ULL;
        ((unsigned long long*)wp1)[tid] = 0xFFFFFFFF00000000ULL;
    }
    if (tid < 2)  dec[tid] = 0xFFFFFFFFu;
    if (tid < 16) xw[tid]  = 0xFFFFFFFF00000000ULL;
    __syncthreads();
    cluster_barrier();   // everyone's slots visible before any remote store

    volatile unsigned int*       decv = dec;
    volatile unsigned long long* xwv  = xw;

    if (wid < NWW) {
        // ================= worker warps =================
        const int base = (int)rank * (WTH * EPT) + tid;   // + e*WTH
        float a[EPT], h[EPT], h1[EPT];
        // deep register prefetch: W distance 4, V distance 4
        float wA[EPT], wC[EPT], wN1[EPT], wN2[EPT], wN3[EPT];
        float vC[EPT], vN1[EPT], vN2[EPT], vN3[EPT];

        #pragma unroll
        for (int e = 0; e < EPT; e++) {
            int j   = base + e * WTH;
            a[e]    = g_a0[j];
            h[e]    = sigmoidf_fast(a[e]);
            h1[e]   = h[e];
            wA[e]   = 0.f;
            wC[e]   = g_Wt[j];                          // W_0   (used at p=1)
            wN1[e]  = g_Wt[(size_t)1 * H + j];          // W_1
            wN2[e]  = g_Wt[(size_t)2 * H + j];          // W_2
            wN3[e]  = g_Wt[(size_t)3 * H + j];          // W_3
            vC[e]   = V[(size_t)1 * H + j];             // V_1   (used at p=1)
            vN1[e]  = V[(size_t)2 * H + j];             // V_2
            vN2[e]  = V[(size_t)3 * H + j];             // V_3
            vN3[e]  = V[(size_t)4 * H + j];             // V_4
        }

        // prologue: partial for step 0 = V_0 . h
        {
            float e0 = 0.f;
            #pragma unroll
            for (int e = 0; e < EPT; e++)
                e0 = fmaf(V[base + e * WTH], h[e], e0);
            #pragma unroll
            for (int o = 16; o > 0; o >>= 1)
                e0 += __shfl_xor_sync(FULL, e0, o);
            if (lane == 0) {
                unsigned long long pk = (unsigned long long)__float_as_uint(e0); // tag 0
                ((volatile unsigned long long*)wp0[0])[wid] = pk;
                ((volatile unsigned long long*)wp1[0])[wid] = pk;
            }
        }

        #pragma unroll 4
        for (int p = 1; p < S; p++) {
            // issue far-ahead prefetches first (fly during the dec wait)
            int pw = (p + 3 < S) ? p + 3 : S - 1;   // W row used at iter p+4
            int pv = (p + 4 < S) ? p + 4 : S - 1;   // V row used at iter p+4
            float wf[EPT], vf[EPT];
            #pragma unroll
            for (int e = 0; e < EPT; e++) {
                wf[e] = g_Wt[(size_t)pw * H + base + e * WTH];
                vf[e] = V[(size_t)pv * H + base + e * WTH];
            }

            if (p >= 2) {
                const unsigned want = (unsigned)(p - 2);
                unsigned d;
                do { d = decv[(p - 2) & 1]; } while ((d >> 1) != want);
                float sm = (float)(d & 1);
                bool  sb = (d & 1);
                #pragma unroll
                for (int e = 0; e < EPT; e++) {
                    a[e] = fmaf(sm, wA[e], a[e]);
                    h[e] = sb ? h1[e] : h[e];
                }
            }

            float e0 = 0.f, e1 = 0.f;
            #pragma unroll
            for (int e = 0; e < EPT; e++) {
                h1[e] = sigmoidf_fast(a[e] + wC[e]);
                e0 = fmaf(vC[e], h[e],  e0);
                e1 = fmaf(vC[e], h1[e], e1);
            }
            #pragma unroll
            for (int o = 16; o > 0; o >>= 1) {
                e0 += __shfl_xor_sync(FULL, e0, o);
                e1 += __shfl_xor_sync(FULL, e1, o);
            }
            if (lane == 0) {
                unsigned long long tg = (unsigned long long)(unsigned)p << 32;
                ((volatile unsigned long long*)wp0[p & 1])[wid] = tg | __float_as_uint(e0);
                ((volatile unsigned long long*)wp1[p & 1])[wid] = tg | __float_as_uint(e1);
            }
            // rotate buffers (unroll-4 lets ptxas rename, not copy)
            #pragma unroll
            for (int e = 0; e < EPT; e++) {
                wA[e] = wC[e]; wC[e] = wN1[e]; wN1[e] = wN2[e]; wN2[e] = wN3[e]; wN3[e] = wf[e];
                vC[e] = vN1[e]; vN1[e] = vN2[e]; vN2[e] = vN3[e]; vN3[e] = vf[e];
            }
        }
    } else if (wid == NWW) {
        // ================= coordinator warp =================
        auto gather = [&](int step, float& Q0, float& Q1) {
            const unsigned want = (unsigned)step;
            const int par = step & 1;
            unsigned long long v = 0;
            if      (lane < 8)  v = ((volatile unsigned long long*)wp0[par])[lane];
            else if (lane < 16) v = ((volatile unsigned long long*)wp1[par])[lane - 8];
            while (!__all_sync(FULL, (lane >= 16) || ((unsigned)(v >> 32) == want))) {
                if      (lane < 8)  v = ((volatile unsigned long long*)wp0[par])[lane];
                else if (lane < 16) v = ((volatile unsigned long long*)wp1[par])[lane - 8];
            }
            float f = (lane < 16) ? __uint_as_float((unsigned)v) : 0.f;
            f += __shfl_xor_sync(FULL, f, 1);
            f += __shfl_xor_sync(FULL, f, 2);
            f += __shfl_xor_sync(FULL, f, 4);
            Q0 = f;
            Q1 = __shfl_xor_sync(FULL, f, 8);
        };

        float  bc = b[0],        bn = b[1];
        float2 tc = g_thr2[0],   tn = g_thr2[1];

        // prologue: send step-0 partial (both branches equal)
        {
            float q0, q1;
            gather(0, q0, q1);
            if (lane < 8) {
                unsigned long long pk = (unsigned long long)__float_as_uint(q0); // tag 0
                remote_store64(smem_u32(&slots[0][rank]), (unsigned)lane, pk);
            }
        }

        for (int i = 0; i < S; i++) {
            float q0n = 0.f, q1n = 0.f;
            if (i + 1 < S) gather(i + 1, q0n, q1n);   // usually ready; overlaps wait

            // poll the 8 remote slots for step i
            const unsigned want = (unsigned)i;
            unsigned long long sv = 0;
            if (lane < 8) sv = slot_ld(&slots[i & 1][lane]);
            while (!__all_sync(FULL, (lane >= 8) || ((unsigned)(sv >> 32) == want))) {
                if (lane < 8) sv = slot_ld(&slots[i & 1][lane]);
            }
            float D = (lane < 8) ? __uint_as_float((unsigned)sv) : 0.f;
            D += __shfl_xor_sync(FULL, D, 1);
            D += __shfl_xor_sync(FULL, D, 2);
            D += __shfl_xor_sync(FULL, D, 4);     // lanes 0-7: identical full sum

            float x = bc + D;
            bool  s = thr_cmp(x, tc);

            if ((i + 1 < S) && lane < 8) {        // critical tail: send first
                float dsel = s ? q1n : q0n;
                unsigned long long pk =
                    ((unsigned long long)(unsigned)(i + 1) << 32) |
                    (unsigned long long)__float_as_uint(dsel);
                remote_store64(smem_u32(&slots[(i + 1) & 1][rank]), (unsigned)lane, pk);
            }
            if (lane == 0) {
                decv[i & 1]  = ((unsigned)i << 1) | (unsigned)s;
                xwv[i & 15]  = ((unsigned long long)(unsigned)i << 32) |
                               (unsigned long long)__float_as_uint(x);
            }

            int ip = (i + 2 < S) ? i + 2 : S - 1;
            float bf = b[ip]; float2 tf = g_thr2[ip];
            bc = bn; bn = bf; tc = tn; tn = tf;
        }
    } else {
        // ================= logp/output warp (rank 0, lane 0 only) =================
        if (rank == 0 && lane == 0) {
            float2 tc = g_thr2[0], tn = g_thr2[1];
            double lp = 0.0;
            for (int i = 0; i < S; i++) {
                unsigned long long xv;
                do { xv = xwv[i & 15]; } while ((unsigned)(xv >> 32) != (unsigned)i);
                float x = __uint_as_float((unsigned)xv);
                bool  s = thr_cmp(x, tc);
                out[i] = s ? 1.0f : 0.0f;
                if (i < S - 2)
                    lp -= (double)(s ? softplusf(-x) : softplusf(x));
                int ip = (i + 2 < S) ? i + 2 : S - 1;
                float2 tf = g_thr2[ip];
                tc = tn; tn = tf;
            }
            out[S] = (float)lp;
            for (int k = S + 1; k < out_size; k++) out[k] = 0.f;
        }
    }

    cluster_barrier();   // no CTA exits while peers may still store to its smem
}

// ---------------- launch ----------------
extern "C" void kernel_launch(void* const* d_in, const int* in_sizes, int n_in,
                              void* d_out, int out_size) {
    const float* ctxv = nullptr;
    const float* u    = nullptr;
    const float* W    = nullptr;
    const float* V    = nullptr;
    const float* b    = nullptr;
    const float* c    = nullptr;

    const int szW = (CTX + S) * H;   // 67108864
    const int szV = S * H;           // 33554432
    int n4seen = 0;
    for (int idx = 0; idx < n_in; idx++) {
        int sz = in_sizes[idx];
        const float* p = (const float*)d_in[idx];
        if (sz == szW)       W = p;
        else if (sz == szV)  V = p;
        else if (sz == H)    c = p;
        else if (sz == S) {
            if      (n4seen == 0) ctxv = p;
            else if (n4seen == 1) u    = p;
            else                  b    = p;
            n4seen++;
        }
    }
    if (!ctxv) ctxv = (const float*)d_in[0];
    if (!u)    u    = (const float*)d_in[1];
    if (!W)    W    = (const float*)d_in[2];
    if (!V)    V    = (const float*)d_in[3];
    if (!b)    b    = (const float*)d_in[4];
    if (!c)    c    = (const float*)d_in[5];

    float* out = (float*)d_out;

    gemv_kernel<<<H, 256>>>(W, ctxv, c);
    transpose_kernel<<<dim3(S / 32, H / 32), dim3(32, 8)>>>(W);
    thr_kernel<<<(S + 255) / 256, 256>>>(u);
    nade_kernel<<<CSZ, TPB>>>(V, b, out, out_size);
}

// round 5
// speedup vs baseline: 2.5835x; 1.4116x over previous
#include <cuda_runtime.h>
#include <cstdint>
#include <math.h>

#define H    8192      // DIM_HIDDEN
#define S    4096      // DIM_SOL (steps)
#define CTX  4096      // DIM_CONTEXT
#define CSZ  8         // cluster size
#define NWW  8         // worker warps per CTA
#define WTH  256       // worker threads per CTA
#define EPT  4         // hidden elems per worker thread (256*4*8 = 8192)
#define TPB  320       // 8 worker warps + coordinator (wid 8) + logp (wid 9)
#define RDEP 4         // recv ring depth (>= cluster skew bound + 2)

// ---------------- device scratch (static, no allocs) ----------------
__device__ float  g_Wt[(size_t)S * H];   // transposed W[:, CTX:]
__device__ float  g_a0[H];               // a0 = c + W[:, :CTX] @ context
__device__ float2 g_thr2[S];             // (t_hi, t_lo) two-float logit(u_i)

// ---------------- helpers ----------------
__device__ __forceinline__ float sigmoidf_fast(float x) {
    return __fdividef(1.0f, 1.0f + __expf(-x));
}
__device__ __forceinline__ float softplusf(float y) {
    float t = fabsf(y);
    float r = log1pf(__expf(-t));
    return (y > 0.f) ? (y + r) : r;
}
__device__ __forceinline__ unsigned cluster_rank() {
    unsigned r; asm("mov.u32 %0, %%cluster_ctarank;" : "=r"(r)); return r;
}
__device__ __forceinline__ uint32_t smem_u32(const void* p) {
    return (uint32_t)__cvta_generic_to_shared(p);
}
__device__ __forceinline__ void remote_store64(uint32_t laddr, unsigned rank, unsigned long long v) {
    uint32_t raddr;
    asm volatile("mapa.shared::cluster.u32 %0, %1, %2;" : "=r"(raddr) : "r"(laddr), "r"(rank));
    asm volatile("st.relaxed.cluster.shared::cluster.b64 [%0], %1;" :: "r"(raddr), "l"(v) : "memory");
}
__device__ __forceinline__ unsigned long long slot_ld(const unsigned long long* p) {
    unsigned long long v;
    uint32_t a = smem_u32(p);
    asm volatile("ld.relaxed.cluster.shared::cta.b64 %0, [%1];" : "=l"(v) : "r"(a) : "memory");
    return v;
}
__device__ __forceinline__ void cluster_barrier() {
    asm volatile("barrier.cluster.arrive.aligned;" ::: "memory");
    asm volatile("barrier.cluster.wait.aligned;"   ::: "memory");
}
// threshold compare: s = (x > t) with t = t_hi + t_lo (x is exact fp32)
__device__ __forceinline__ bool thr_cmp(float x, float2 t) {
    return (x > t.x) || ((x == t.x) && (t.y < 0.f));
}

// ---------------- init kernel 1: a0 = c + W[:, :CTX] @ context ----------------
__global__ void gemv_kernel(const float* __restrict__ W,
                            const float* __restrict__ ctxv,
                            const float* __restrict__ c) {
    __shared__ float sred[256];
    int r = blockIdx.x;
    const float* row = W + (size_t)r * (CTX + S);
    float acc = 0.f;
    for (int k = threadIdx.x; k < CTX; k += 256)
        acc += row[k] * ctxv[k];
    sred[threadIdx.x] = acc;
    __syncthreads();
    for (int off = 128; off > 0; off >>= 1) {
        if (threadIdx.x < off) sred[threadIdx.x] += sred[threadIdx.x + off];
        __syncthreads();
    }
    if (threadIdx.x == 0) g_a0[r] = c[r] + sred[0];
}

// ---------------- init kernel 2: transpose W[:, CTX:] -> g_Wt ----------------
__global__ void transpose_kernel(const float* __restrict__ W) {
    __shared__ float tile[32][33];
    int i0 = blockIdx.x * 32;   // step index base
    int j0 = blockIdx.y * 32;   // hidden index base
    int tx = threadIdx.x;
    #pragma unroll
    for (int t = 0; t < 4; t++) {
        int ty = threadIdx.y + t * 8;
        tile[ty][tx] = W[(size_t)(j0 + ty) * (CTX + S) + CTX + i0 + tx];
    }
    __syncthreads();
    #pragma unroll
    for (int t = 0; t < 4; t++) {
        int ty = threadIdx.y + t * 8;
        g_Wt[(size_t)(i0 + ty) * H + j0 + tx] = tile[tx][ty];
    }
}

// ---------------- init kernel 3: two-float thresholds ----------------
__global__ void thr_kernel(const float* __restrict__ u) {
    int i = blockIdx.x * 256 + threadIdx.x;
    if (i < S) {
        double ud = (double)u[i];
        double t  = log(ud / (1.0 - ud));
        float hi  = (float)t;
        float lo  = (float)(t - (double)hi);
        g_thr2[i] = make_float2(hi, lo);
    }
}

// ---------------- main sequential kernel: 8-CTA cluster ----------------
// recv layout per ring slot: [0..63]   = e0 words (srcCTA*8 + warp), tag in hi32
//                            [64..127] = e1 words (same index + 64)
__global__ void __cluster_dims__(CSZ, 1, 1) __launch_bounds__(TPB, 1)
nade_kernel(const float* __restrict__ V,
            const float* __restrict__ b,
            float* __restrict__ out,
            int out_size) {
    __shared__ unsigned long long recv[RDEP][128];  // worker-pair broadcast slots
    __shared__ unsigned int       dec[2];           // decision word: (step<<1)|s
    __shared__ unsigned long long xw[S];            // x per step (tagged) — no reuse

    const unsigned rank = cluster_rank();
    const int tid  = threadIdx.x;
    const int wid  = tid >> 5;
    const int lane = tid & 31;
    const unsigned FULL = 0xffffffffu;

    for (int k = tid; k < RDEP * 128; k += TPB)
        ((unsigned long long*)recv)[k] = 0xFFFFFFFF00000000ULL;
    if (tid < 2) dec[tid] = 0xFFFFFFFFu;
    for (int k = tid; k < S; k += TPB)
        xw[k] = 0xFFFFFFFF00000000ULL;
    __syncthreads();
    cluster_barrier();   // everyone's recv initialized before any remote store

    volatile unsigned int*       decv = dec;
    volatile unsigned long long* xwv  = xw;

    if (wid < NWW) {
        // ================= worker warps =================
        const int base = (int)rank * (WTH * EPT) + tid;   // + e*WTH
        const int slotA = (int)rank * 8 + wid;            // e0 slot index
        float a[EPT], h[EPT], h1[EPT];
        // deep register prefetch: distance 4
        float wPrev[EPT], wC[EPT], wN1[EPT], wN2[EPT], wN3[EPT];
        float vC[EPT], vN1[EPT], vN2[EPT], vN3[EPT];

        #pragma unroll
        for (int e = 0; e < EPT; e++) {
            int j   = base + e * WTH;
            a[e]    = g_a0[j];
            h[e]    = sigmoidf_fast(a[e]);
            wPrev[e]= g_Wt[j];                          // W_0
            wC[e]   = g_Wt[(size_t)1 * H + j];          // W_1
            wN1[e]  = g_Wt[(size_t)2 * H + j];          // W_2
            wN2[e]  = g_Wt[(size_t)3 * H + j];          // W_3
            wN3[e]  = g_Wt[(size_t)4 * H + j];          // W_4
            vC[e]   = V[(size_t)2 * H + j];             // V_2
            vN1[e]  = V[(size_t)3 * H + j];             // V_3
            vN2[e]  = V[(size_t)4 * H + j];             // V_4
            vN3[e]  = V[(size_t)5 * H + j];             // V_5
        }

        // send helper: lanes 0-15 broadcast the tagged pair to all 8 CTAs
        auto send_pair = [&](int p, float e0, float e1) {
            if (lane < 16) {
                float val = (lane < 8) ? e0 : e1;
                int   slot = (lane < 8) ? slotA : (64 + slotA);
                unsigned long long pk =
                    ((unsigned long long)(unsigned)p << 32) |
                    (unsigned long long)__float_as_uint(val);
                remote_store64(smem_u32(&recv[p & (RDEP - 1)][slot]), (unsigned)(lane & 7), pk);
            }
        };

        // prologue: pair(0) = V_0 . h (both branches equal); pair(1) over s_0
        {
            float e0 = 0.f;
            #pragma unroll
            for (int e = 0; e < EPT; e++)
                e0 = fmaf(V[base + e * WTH], h[e], e0);
            #pragma unroll
            for (int o = 16; o > 0; o >>= 1)
                e0 += __shfl_xor_sync(FULL, e0, o);
            send_pair(0, e0, e0);
        }
        {
            float e0 = 0.f, e1 = 0.f;
            #pragma unroll
            for (int e = 0; e < EPT; e++) {
                h1[e] = sigmoidf_fast(a[e] + wPrev[e]);   // sigma(a0 + W_0)
                float v1 = V[(size_t)1 * H + base + e * WTH];
                e0 = fmaf(v1, h[e],  e0);
                e1 = fmaf(v1, h1[e], e1);
            }
            #pragma unroll
            for (int o = 16; o > 0; o >>= 1) {
                e0 += __shfl_xor_sync(FULL, e0, o);
                e1 += __shfl_xor_sync(FULL, e1, o);
            }
            send_pair(1, e0, e1);
        }

        #pragma unroll 4
        for (int p = 2; p < S; p++) {
            // far-ahead prefetches (fly during the dec wait)
            int pw = (p + 3 < S) ? p + 3 : S - 1;   // W row used at iter p+4
            int pv = (p + 4 < S) ? p + 4 : S - 1;   // V row used at iter p+4
            float wf[EPT], vf[EPT];
            #pragma unroll
            for (int e = 0; e < EPT; e++) {
                wf[e] = g_Wt[(size_t)pw * H + base + e * WTH];
                vf[e] = V[(size_t)pv * H + base + e * WTH];
            }

            // consume dec(p-2)
            {
                const unsigned want = (unsigned)(p - 2);
                unsigned d;
                do { d = decv[(p - 2) & 1]; } while ((d >> 1) != want);
                float sm = (float)(d & 1);
                bool  sb = (d & 1);
                #pragma unroll
                for (int e = 0; e < EPT; e++) {
                    a[e] = fmaf(sm, wPrev[e], a[e]);
                    h[e] = sb ? h1[e] : h[e];
                }
            }

            float e0 = 0.f, e1 = 0.f;
            #pragma unroll
            for (int e = 0; e < EPT; e++) {
                h1[e] = sigmoidf_fast(a[e] + wC[e]);   // branch s_{p-1}=1
                e0 = fmaf(vC[e], h[e],  e0);
                e1 = fmaf(vC[e], h1[e], e1);
            }
            #pragma unroll
            for (int o = 16; o > 0; o >>= 1) {
                e0 += __shfl_xor_sync(FULL, e0, o);
                e1 += __shfl_xor_sync(FULL, e1, o);
            }
            send_pair(p, e0, e1);

            // rotate buffers
            #pragma unroll
            for (int e = 0; e < EPT; e++) {
                wPrev[e] = wC[e]; wC[e] = wN1[e]; wN1[e] = wN2[e]; wN2[e] = wN3[e]; wN3[e] = wf[e];
                vC[e] = vN1[e]; vN1[e] = vN2[e]; vN2[e] = vN3[e]; vN3[e] = vf[e];
            }
        }
    } else if (wid == NWW) {
        // ================= coordinator warp =================
        float  bc = b[0],      bn = b[1];
        float2 tc = g_thr2[0], tn = g_thr2[1];
        unsigned sprev = 0;

        for (int i = 0; i < S; i++) {
            const unsigned want = (unsigned)i;
            const unsigned long long* rb = (const unsigned long long*)recv[i & (RDEP - 1)];

            // poll my 4 words (2 e0-slots, 2 e1-slots)
            unsigned long long a0, a1, b0, b1;
            bool ok;
            do {
                a0 = slot_ld(rb + 2 * lane);
                a1 = slot_ld(rb + 2 * lane + 1);
                b0 = slot_ld(rb + 64 + 2 * lane);
                b1 = slot_ld(rb + 64 + 2 * lane + 1);
                ok = ((unsigned)(a0 >> 32) == want) & ((unsigned)(a1 >> 32) == want)
                   & ((unsigned)(b0 >> 32) == want) & ((unsigned)(b1 >> 32) == want);
            } while (!__all_sync(FULL, ok));

            // fixed-order reduce of both branches (identical in all CTAs)
            float e0 = __uint_as_float((unsigned)a0) + __uint_as_float((unsigned)a1);
            float e1 = __uint_as_float((unsigned)b0) + __uint_as_float((unsigned)b1);
            #pragma unroll
            for (int o = 16; o > 0; o >>= 1) {
                e0 += __shfl_xor_sync(FULL, e0, o);
                e1 += __shfl_xor_sync(FULL, e1, o);
            }

            // tiny recurrence tail: select by s_{i-1}, compare, publish
            float D = sprev ? e1 : e0;
            float x = bc + D;
            bool  s = thr_cmp(x, tc);
            sprev = (unsigned)s;

            if (lane == 0) {
                decv[i & 1] = ((unsigned)i << 1) | (unsigned)s;
                xwv[i]      = ((unsigned long long)(unsigned)i << 32) |
                              (unsigned long long)__float_as_uint(x);
            }

            int ip = (i + 2 < S) ? i + 2 : S - 1;
            float bf = b[ip]; float2 tf = g_thr2[ip];
            bc = bn; bn = bf; tc = tn; tn = tf;
        }
    } else {
        // ================= logp/output warp (rank 0, lane 0 only) =================
        if (rank == 0 && lane == 0) {
            float2 tc = g_thr2[0], tn = g_thr2[1];
            double lp = 0.0;
            for (int i = 0; i < S; i++) {
                unsigned long long xv;
                do { xv = xwv[i]; } while ((unsigned)(xv >> 32) != (unsigned)i);
                float x = __uint_as_float((unsigned)xv);
                bool  s = thr_cmp(x, tc);
                out[i] = s ? 1.0f : 0.0f;
                if (i < S - 2)
                    lp -= (double)(s ? softplusf(-x) : softplusf(x));
                int ip = (i + 2 < S) ? i + 2 : S - 1;
                float2 tf = g_thr2[ip];
                tc = tn; tn = tf;
            }
            out[S] = (float)lp;
            for (int k = S + 1; k < out_size; k++) out[k] = 0.f;
        }
    }

    cluster_barrier();   // no CTA exits while peers may still store to its smem
}

// ---------------- launch ----------------
extern "C" void kernel_launch(void* const* d_in, const int* in_sizes, int n_in,
                              void* d_out, int out_size) {
    const float* ctxv = nullptr;
    const float* u    = nullptr;
    const float* W    = nullptr;
    const float* V    = nullptr;
    const float* b    = nullptr;
    const float* c    = nullptr;

    const int szW = (CTX + S) * H;   // 67108864
    const int szV = S * H;           // 33554432
    int n4seen = 0;
    for (int idx = 0; idx < n_in; idx++) {
        int sz = in_sizes[idx];
        const float* p = (const float*)d_in[idx];
        if (sz == szW)       W = p;
        else if (sz == szV)  V = p;
        else if (sz == H)    c = p;
        else if (sz == S) {
            if      (n4seen == 0) ctxv = p;
            else if (n4seen == 1) u    = p;
            else                  b    = p;
            n4seen++;
        }
    }
    if (!ctxv) ctxv = (const float*)d_in[0];
    if (!u)    u    = (const float*)d_in[1];
    if (!W)    W    = (const float*)d_in[2];
    if (!V)    V    = (const float*)d_in[3];
    if (!b)    b    = (const float*)d_in[4];
    if (!c)    c    = (const float*)d_in[5];

    float* out = (float*)d_out;

    gemv_kernel<<<H, 256>>>(W, ctxv, c);
    transpose_kernel<<<dim3(S / 32, H / 32), dim3(32, 8)>>>(W);
    thr_kernel<<<(S + 255) / 256, 256>>>(u);
    nade_kernel<<<CSZ, TPB>>>(V, b, out, out_size);
}